// round 1
// baseline (speedup 1.0000x reference)
#include <cuda_runtime.h>

// quadLayer: out[b,h,w, c*512 + a*32 + f] =
//   sum_m p[a][m] * W1[c][m][f] + sum_{m1,m2} p[a][m1]*p[a][m2] * W2[c][m1*4+m2][f]
// where p[a][mm] = x[b, 2h + ((a>>2)>>1), 2w + ((a>>2)&1), ((4a)&15)+mm]
// (raw reshape of the (ki,kj,c)-ordered patch depth; p row a is a single float4 of x).
//
// Strategy: 20-feature vector per (pixel, a) in SMEM, interleaved over a-parity so
// ld.shared.v2.u64 yields {feat[2ap][k], feat[2ap+1][k]} pairs directly; weights
// live in registers as duplicated f32x2; inner loop is pure fma.rn.f32x2 (FFMA2).

#define NPIX 8          // pixels per block
#define THREADS 512     // c (16) x f (32)

__device__ __forceinline__ unsigned long long pack2(float lo, float hi) {
    unsigned long long r;
    asm("mov.b64 %0, {%1,%2};" : "=l"(r) : "f"(lo), "f"(hi));
    return r;
}

__device__ __forceinline__ void fma2(unsigned long long &d,
                                     unsigned long long a,
                                     unsigned long long b) {
    asm("fma.rn.f32x2 %0, %1, %2, %0;" : "+l"(d) : "l"(a), "l"(b));
}

__global__ void __launch_bounds__(THREADS, 2)
quad_kernel(const float* __restrict__ x,
            const float* __restrict__ W1,
            const float* __restrict__ W2,
            float* __restrict__ out)
{
    // feat[pix][ap][k][apar]: (NPIX * 8 apairs * 20 k * 2) floats = 10.24 KB
    __shared__ __align__(16) float feat[NPIX * 8 * 20 * 2];

    const int t = threadIdx.x;
    const int c = t >> 5;    // 0..15
    const int f = t & 31;    // 0..31

    // ---- per-thread weights: W1[c][m][f] (m<4), W2[c][q][f] (q<16) ----
    float w[20];
#pragma unroll
    for (int m = 0; m < 4; m++)  w[m]     = W1[c * 128 + m * 32 + f];
#pragma unroll
    for (int q = 0; q < 16; q++) w[4 + q] = W2[c * 512 + q * 32 + f];
    unsigned long long wp[20];
#pragma unroll
    for (int k = 0; k < 20; k++) wp[k] = pack2(w[k], w[k]);

    // ---- feature build: one thread per (pix, a) ----
    if (t < NPIX * 16) {
        const int pix = t >> 4;
        const int a   = t & 15;
        const int g   = blockIdx.x * NPIX + pix;          // global pixel id
        const int b   = g >> 10;
        const int h   = (g >> 5) & 31;
        const int wc  = g & 31;
        const int m   = a >> 2;
        const int i   = m >> 1;
        const int j   = m & 1;
        const int c0  = (a & 3) * 4;
        const float4 v = *reinterpret_cast<const float4*>(
            x + (((b * 64 + 2 * h + i) * 64) + (2 * wc + j)) * 16 + c0);
        const float p[4] = {v.x, v.y, v.z, v.w};
        float* fb = &feat[((pix * 8 + (a >> 1)) * 20) * 2 + (a & 1)];
#pragma unroll
        for (int k = 0; k < 4; k++) fb[2 * k] = p[k];
#pragma unroll
        for (int m1 = 0; m1 < 4; m1++)
#pragma unroll
            for (int m2 = 0; m2 < 4; m2++)
                fb[2 * (4 + m1 * 4 + m2)] = p[m1] * p[m2];
    }
    __syncthreads();

    const size_t gbase = (size_t)blockIdx.x * NPIX * 8192 + (size_t)(c * 512 + f);
    const unsigned int sbase = (unsigned int)__cvta_generic_to_shared(feat);

#pragma unroll 1
    for (int pix = 0; pix < NPIX; pix++) {
        const size_t obase = gbase + (size_t)pix * 8192;
        const unsigned int pbase = sbase + pix * (8 * 160);
#pragma unroll
        for (int ap = 0; ap < 8; ap++) {
            const unsigned int addr = pbase + ap * 160;  // 20 pairs * 8B
            unsigned long long acc = 0ULL;               // {0.f, 0.f}
#pragma unroll
            for (int kk2 = 0; kk2 < 5; kk2++) {
                unsigned long long p0, p1, p2, p3;
                asm("ld.shared.v2.u64 {%0,%1}, [%2];"
                    : "=l"(p0), "=l"(p1) : "r"(addr + kk2 * 32));
                asm("ld.shared.v2.u64 {%0,%1}, [%2];"
                    : "=l"(p2), "=l"(p3) : "r"(addr + kk2 * 32 + 16));
                fma2(acc, wp[4 * kk2 + 0], p0);
                fma2(acc, wp[4 * kk2 + 1], p1);
                fma2(acc, wp[4 * kk2 + 2], p2);
                fma2(acc, wp[4 * kk2 + 3], p3);
            }
            float lo, hi;
            asm("mov.b64 {%0,%1}, %2;" : "=f"(lo), "=f"(hi) : "l"(acc));
            out[obase + (size_t)((2 * ap) * 32)]     = lo;   // a = 2*ap
            out[obase + (size_t)((2 * ap + 1) * 32)] = hi;   // a = 2*ap+1
        }
    }
}

extern "C" void kernel_launch(void* const* d_in, const int* in_sizes, int n_in,
                              void* d_out, int out_size) {
    const float* x  = (const float*)d_in[0];
    const float* W1 = (const float*)d_in[1];
    const float* W2 = (const float*)d_in[2];
    float* out = (float*)d_out;
    // 8192 pixels total / NPIX per block
    quad_kernel<<<8192 / NPIX, THREADS>>>(x, W1, W2, out);
}

// round 2
// speedup vs baseline: 1.4646x; 1.4646x over previous
#include <cuda_runtime.h>

// quadLayer: out[b,h,w, c*512 + a*32 + f] =
//   sum_m p[a][m] * W1[c][m][f] + sum_{m1,m2} p[a][m1]*p[a][m2] * W2[c][m1*4+m2][f]
// where p[a][mm] = x[b, 2h+((a>>2)>>1), 2w+((a>>2)&1), 4*(a&3)+mm]  (one float4 of x).
//
// R2: each thread owns TWO c-planes (c0, c0+8) so every broadcast shared load
// feeds 2x the FFMA2 work (L1 was the R1 bottleneck at 87%). Features packed
// by a-parity in SMEM; weights duplicated into f32x2 registers; 4 independent
// accumulator chains per thread.

#define NPIX 16         // pixels per block
#define THREADS 256     // 8 c-pairs x 32 f

__device__ __forceinline__ unsigned long long pack2(float lo, float hi) {
    unsigned long long r;
    asm("mov.b64 %0, {%1,%2};" : "=l"(r) : "f"(lo), "f"(hi));
    return r;
}

__device__ __forceinline__ void fma2(unsigned long long &d,
                                     unsigned long long a,
                                     unsigned long long b) {
    asm("fma.rn.f32x2 %0, %1, %2, %0;" : "+l"(d) : "l"(a), "l"(b));
}

__device__ __forceinline__ unsigned long long add2(unsigned long long a,
                                                   unsigned long long b) {
    unsigned long long r;
    asm("add.rn.f32x2 %0, %1, %2;" : "=l"(r) : "l"(a), "l"(b));
    return r;
}

__global__ void __launch_bounds__(THREADS, 2)
quad_kernel(const float* __restrict__ x,
            const float* __restrict__ W1,
            const float* __restrict__ W2,
            float* __restrict__ out)
{
    // feat[pix][ap][k][apar]: NPIX * 8 apairs * 20 k * 2 floats = 20 KB
    __shared__ __align__(16) float feat[NPIX * 8 * 20 * 2];

    const int t  = threadIdx.x;
    const int c0 = t >> 5;   // 0..7  (handles c0 and c0+8)
    const int f  = t & 31;   // 0..31

    // ---- per-thread weights for both c-planes, duplicated into f32x2 ----
    unsigned long long wpA[20], wpB[20];
    {
        const int cA = c0, cB = c0 + 8;
#pragma unroll
        for (int m = 0; m < 4; m++) {
            float a = W1[cA * 128 + m * 32 + f];
            float b = W1[cB * 128 + m * 32 + f];
            wpA[m] = pack2(a, a);
            wpB[m] = pack2(b, b);
        }
#pragma unroll
        for (int q = 0; q < 16; q++) {
            float a = W2[cA * 512 + q * 32 + f];
            float b = W2[cB * 512 + q * 32 + f];
            wpA[4 + q] = pack2(a, a);
            wpB[4 + q] = pack2(b, b);
        }
    }

    // ---- feature build: one thread per (pix, a); 256 threads = NPIX*16 ----
    {
        const int pix = t >> 4;
        const int a   = t & 15;
        const int g   = blockIdx.x * NPIX + pix;          // global pixel id
        const int b   = g >> 10;
        const int h   = (g >> 5) & 31;
        const int wc  = g & 31;
        const int m   = a >> 2;
        const int i   = m >> 1;
        const int j   = m & 1;
        const int ch0 = (a & 3) * 4;
        const float4 v = *reinterpret_cast<const float4*>(
            x + (((b * 64 + 2 * h + i) * 64) + (2 * wc + j)) * 16 + ch0);
        const float p[4] = {v.x, v.y, v.z, v.w};
        float* fb = &feat[((pix * 8 + (a >> 1)) * 20) * 2 + (a & 1)];
#pragma unroll
        for (int k = 0; k < 4; k++) fb[2 * k] = p[k];
#pragma unroll
        for (int m1 = 0; m1 < 4; m1++)
#pragma unroll
            for (int m2 = 0; m2 < 4; m2++)
                fb[2 * (4 + m1 * 4 + m2)] = p[m1] * p[m2];
    }
    __syncthreads();

    const size_t gbase = (size_t)blockIdx.x * NPIX * 8192 + (size_t)f;
    const int cOffA = c0 * 512;
    const int cOffB = (c0 + 8) * 512;
    const unsigned int sbase = (unsigned int)__cvta_generic_to_shared(feat);

#pragma unroll 1
    for (int pix = 0; pix < NPIX; pix++) {
        const size_t obase = gbase + (size_t)pix * 8192;
        const unsigned int pbase = sbase + pix * (8 * 160);
#pragma unroll
        for (int ap = 0; ap < 8; ap++) {
            const unsigned int addr = pbase + ap * 160;   // 20 pairs * 8B
            unsigned long long aA0 = 0ULL, aA1 = 0ULL;
            unsigned long long aB0 = 0ULL, aB1 = 0ULL;
#pragma unroll
            for (int kk = 0; kk < 5; kk++) {
                unsigned long long p0, p1, p2, p3;
                asm("ld.shared.v2.u64 {%0,%1}, [%2];"
                    : "=l"(p0), "=l"(p1) : "r"(addr + kk * 32));
                asm("ld.shared.v2.u64 {%0,%1}, [%2];"
                    : "=l"(p2), "=l"(p3) : "r"(addr + kk * 32 + 16));
                fma2(aA0, wpA[4 * kk + 0], p0);
                fma2(aA1, wpA[4 * kk + 1], p1);
                fma2(aB0, wpB[4 * kk + 0], p0);
                fma2(aB1, wpB[4 * kk + 1], p1);
                fma2(aA0, wpA[4 * kk + 2], p2);
                fma2(aA1, wpA[4 * kk + 3], p3);
                fma2(aB0, wpB[4 * kk + 2], p2);
                fma2(aB1, wpB[4 * kk + 3], p3);
            }
            const unsigned long long aA = add2(aA0, aA1);
            const unsigned long long aB = add2(aB0, aB1);
            float lA, hA, lB, hB;
            asm("mov.b64 {%0,%1}, %2;" : "=f"(lA), "=f"(hA) : "l"(aA));
            asm("mov.b64 {%0,%1}, %2;" : "=f"(lB), "=f"(hB) : "l"(aB));
            out[obase + (size_t)(cOffA + (2 * ap) * 32)]     = lA;
            out[obase + (size_t)(cOffA + (2 * ap + 1) * 32)] = hA;
            out[obase + (size_t)(cOffB + (2 * ap) * 32)]     = lB;
            out[obase + (size_t)(cOffB + (2 * ap + 1) * 32)] = hB;
        }
    }
}

extern "C" void kernel_launch(void* const* d_in, const int* in_sizes, int n_in,
                              void* d_out, int out_size) {
    const float* x  = (const float*)d_in[0];
    const float* W1 = (const float*)d_in[1];
    const float* W2 = (const float*)d_in[2];
    float* out = (float*)d_out;
    quad_kernel<<<8192 / NPIX, THREADS>>>(x, W1, W2, out);
}